// round 3
// baseline (speedup 1.0000x reference)
#include <cuda_runtime.h>

// DSAttention (de-stationary attention), fp32 flash-attention with packed
// f32x2 FFMA2 (Blackwell-only; ptxas never emits it from C++).
// B=2, L=S=2048, H=16, E=D=64.
// logits = 0.125*(tau[b]*(q·k) + delta[b,s]); out = softmax(logits) @ V

namespace {

constexpr int B_ = 2, L_ = 2048, S_ = 2048, H_ = 16, E_ = 64, D_ = 64;
constexpr int TM = 64;        // query rows per block
constexpr int TN = 64;        // key/value rows per tile
constexpr int STRIDE = 68;    // padded smem row stride (17 x float4: aligned + conflict-free)
constexpr int THREADS = 256;  // logical 16x16: ty = t>>4 (rows), tx = t&15 (cols)

constexpr size_t SMEM_FLOATS = (size_t)4 * TM * STRIDE + TN;  // Qs,Ks,Vs,Ps + dls
constexpr size_t SMEM_BYTES  = SMEM_FLOATS * sizeof(float);

union F4U2 { float4 f; unsigned long long u[2]; };

__device__ __forceinline__ unsigned long long fma2(
    unsigned long long a, unsigned long long b, unsigned long long c) {
    unsigned long long d;
    asm("fma.rn.f32x2 %0, %1, %2, %3;" : "=l"(d) : "l"(a), "l"(b), "l"(c));
    return d;
}
__device__ __forceinline__ unsigned long long mul2(
    unsigned long long a, unsigned long long b) {
    unsigned long long d;
    asm("mul.rn.f32x2 %0, %1, %2;" : "=l"(d) : "l"(a), "l"(b));
    return d;
}
__device__ __forceinline__ unsigned long long pack2(float lo, float hi) {
    unsigned long long d;
    asm("mov.b64 %0, {%1, %2};" : "=l"(d) : "f"(lo), "f"(hi));
    return d;
}
__device__ __forceinline__ float2 unpack2(unsigned long long v) {
    float2 r;
    asm("mov.b64 {%0, %1}, %2;" : "=f"(r.x), "=f"(r.y) : "l"(v));
    return r;
}

__global__ __launch_bounds__(THREADS, 2) void dsattn_kernel(
    const float* __restrict__ Q, const float* __restrict__ K,
    const float* __restrict__ V, const float* __restrict__ Tau,
    const float* __restrict__ Delta, float* __restrict__ Out)
{
    extern __shared__ float sm[];
    float* Qs  = sm;                    // [TM][STRIDE]
    float* Ks  = Qs + TM * STRIDE;      // [TN][STRIDE]
    float* Vs  = Ks + TN * STRIDE;      // [TN][STRIDE]
    float* Ps  = Vs + TN * STRIDE;      // [TM][STRIDE]
    float* dls = Ps + TM * STRIDE;      // [TN]

    const int t  = threadIdx.x;
    const int ty = t >> 4;              // rows 4*ty .. 4*ty+3
    const int tx = t & 15;              // GEMM1 cols: tx+16j; GEMM2 cols: {2tx,2tx+1},{2tx+32,2tx+33}
    const int bh = blockIdx.y;
    const int b  = bh / H_;
    const int h  = bh - b * H_;
    const int l0 = blockIdx.x * TM;

    const float qscale = 0.125f * Tau[b];
    const float* qb = Q + (((size_t)b * L_) * H_ + h) * E_;
    const float* kb = K + (((size_t)b * S_) * H_ + h) * E_;
    const float* vb = V + (((size_t)b * S_) * H_ + h) * D_;
    const float* db = Delta + (size_t)b * S_;

    // Load Q tile, fold in 0.125*tau
    #pragma unroll
    for (int i = 0; i < 4; ++i) {
        int idx = t + i * THREADS;          // [64 rows][16 float4]
        int m = idx >> 4, e4 = idx & 15;
        float4 a = *(const float4*)(qb + (size_t)(l0 + m) * (H_ * E_) + e4 * 4);
        float* d = &Qs[m * STRIDE + e4 * 4];
        d[0] = a.x * qscale; d[1] = a.y * qscale;
        d[2] = a.z * qscale; d[3] = a.w * qscale;
    }

    float mrow[4], lrow[4];
    unsigned long long acc2[4][2];      // packed output cols: jj=0 -> {2tx,2tx+1}, jj=1 -> +32
    #pragma unroll
    for (int i = 0; i < 4; ++i) {
        mrow[i] = -1e30f; lrow[i] = 0.0f;
        acc2[i][0] = 0ull; acc2[i][1] = 0ull;
    }

    for (int s0 = 0; s0 < S_; s0 += TN) {
        __syncthreads();  // previous GEMM2 done reading Ps/Vs

        // Fill K, V tiles (coalesced float4)
        #pragma unroll
        for (int i = 0; i < 4; ++i) {
            int idx = t + i * THREADS;
            int s = idx >> 4, e4 = idx & 15;
            *(float4*)(&Ks[s * STRIDE + e4 * 4]) =
                *(const float4*)(kb + (size_t)(s0 + s) * (H_ * E_) + e4 * 4);
            *(float4*)(&Vs[s * STRIDE + e4 * 4]) =
                *(const float4*)(vb + (size_t)(s0 + s) * (H_ * D_) + e4 * 4);
        }
        if (t < TN) dls[t] = 0.125f * db[s0 + t];
        __syncthreads();

        // ---- GEMM1 (packed k-pairs): sc[i][j] = Qs[4ty+i] . Ks[tx+16j] ----
        unsigned long long sc2[4][4];
        #pragma unroll
        for (int i = 0; i < 4; ++i)
            #pragma unroll
            for (int j = 0; j < 4; ++j) sc2[i][j] = 0ull;

        #pragma unroll
        for (int k4 = 0; k4 < 16; ++k4) {
            F4U2 a[4], bb[4];
            #pragma unroll
            for (int i = 0; i < 4; ++i)
                a[i].f = *(const float4*)(&Qs[(4 * ty + i) * STRIDE + 4 * k4]);
            #pragma unroll
            for (int j = 0; j < 4; ++j)
                bb[j].f = *(const float4*)(&Ks[(tx + 16 * j) * STRIDE + 4 * k4]);
            #pragma unroll
            for (int i = 0; i < 4; ++i)
                #pragma unroll
                for (int j = 0; j < 4; ++j) {
                    sc2[i][j] = fma2(a[i].u[0], bb[j].u[0], sc2[i][j]);
                    sc2[i][j] = fma2(a[i].u[1], bb[j].u[1], sc2[i][j]);
                }
        }

        float sc[4][4];
        #pragma unroll
        for (int j = 0; j < 4; ++j) {
            float dl = dls[tx + 16 * j];
            #pragma unroll
            for (int i = 0; i < 4; ++i) {
                float2 p = unpack2(sc2[i][j]);
                sc[i][j] = p.x + p.y + dl;
            }
        }

        // ---- online softmax (row groups = contiguous 16-lane halves) ----
        #pragma unroll
        for (int i = 0; i < 4; ++i) {
            float mx = fmaxf(fmaxf(sc[i][0], sc[i][1]), fmaxf(sc[i][2], sc[i][3]));
            #pragma unroll
            for (int w = 1; w < 16; w <<= 1)
                mx = fmaxf(mx, __shfl_xor_sync(0xffffffffu, mx, w));
            float mn   = fmaxf(mrow[i], mx);
            float corr = __expf(mrow[i] - mn);
            mrow[i] = mn;

            float rs = 0.0f;
            #pragma unroll
            for (int j = 0; j < 4; ++j) {
                float p = __expf(sc[i][j] - mn);
                Ps[(4 * ty + i) * STRIDE + tx + 16 * j] = p;  // conflict-free scatter
                rs += p;
            }
            #pragma unroll
            for (int w = 1; w < 16; w <<= 1)
                rs += __shfl_xor_sync(0xffffffffu, rs, w);
            lrow[i] = lrow[i] * corr + rs;

            unsigned long long cp = pack2(corr, corr);
            acc2[i][0] = mul2(acc2[i][0], cp);
            acc2[i][1] = mul2(acc2[i][1], cp);
        }
        __syncthreads();

        // ---- GEMM2 (packed col-pairs): acc += P[row][s] * V[s][colpair] ----
        #pragma unroll 8
        for (int s = 0; s < TN; ++s) {
            unsigned long long vv0 = *(const unsigned long long*)(&Vs[s * STRIDE + 2 * tx]);
            unsigned long long vv1 = *(const unsigned long long*)(&Vs[s * STRIDE + 2 * tx + 32]);
            #pragma unroll
            for (int i = 0; i < 4; ++i) {
                float p = Ps[(4 * ty + i) * STRIDE + s];     // broadcast
                unsigned long long pd = pack2(p, p);
                acc2[i][0] = fma2(pd, vv0, acc2[i][0]);
                acc2[i][1] = fma2(pd, vv1, acc2[i][1]);
            }
        }
    }

    // Epilogue: normalize and store [B,L,H,D] (float2, coalesced)
    #pragma unroll
    for (int i = 0; i < 4; ++i) {
        float inv = 1.0f / lrow[i];
        size_t row = (((size_t)b * L_ + (l0 + 4 * ty + i)) * H_ + h) * (size_t)D_;
        float2 o0 = unpack2(acc2[i][0]);
        float2 o1 = unpack2(acc2[i][1]);
        o0.x *= inv; o0.y *= inv; o1.x *= inv; o1.y *= inv;
        *(float2*)(&Out[row + 2 * tx])      = o0;
        *(float2*)(&Out[row + 2 * tx + 32]) = o1;
    }
}

}  // namespace

extern "C" void kernel_launch(void* const* d_in, const int* /*in_sizes*/, int /*n_in*/,
                              void* d_out, int /*out_size*/) {
    const float* q     = (const float*)d_in[0];
    const float* k     = (const float*)d_in[1];
    const float* v     = (const float*)d_in[2];
    const float* tau   = (const float*)d_in[3];
    const float* delta = (const float*)d_in[4];
    // d_in[5] = attn_mask, unused (mask_flag=False in reference)

    cudaFuncSetAttribute(dsattn_kernel,
                         cudaFuncAttributeMaxDynamicSharedMemorySize,
                         (int)SMEM_BYTES);

    dim3 grid(L_ / TM, B_ * H_);  // x = q-tile (fast) so one (b,h)'s K/V stays hot in L2
    dsattn_kernel<<<grid, THREADS, SMEM_BYTES>>>(q, k, v, tau, delta, (float*)d_out);
}